// round 14
// baseline (speedup 1.0000x reference)
#include <cuda_runtime.h>

#define HH 512
#define WW 1024
#define DD 32
#define HWSZ (HH*WW)

typedef unsigned long long u64;

// Packed RGBA (A unused) copies of the two source views. 16 MB static scratch.
__device__ float4 g_img[2][HWSZ];

__global__ void pack_kernel(const float* __restrict__ ref, const float* __restrict__ inp) {
    int i = blockIdx.x * blockDim.x + threadIdx.x;   // quad index
    if (i >= HWSZ / 4) return;
    const float4* r4 = (const float4*)ref;
    const float4* i4 = (const float4*)inp;
    float4 a0 = r4[i], a1 = r4[i + HWSZ/4], a2 = r4[i + 2*(HWSZ/4)];
    float4 b0 = i4[i], b1 = i4[i + HWSZ/4], b2 = i4[i + 2*(HWSZ/4)];
    int o = i << 2;
    g_img[0][o+0] = make_float4(a0.x, a1.x, a2.x, 0.f);
    g_img[0][o+1] = make_float4(a0.y, a1.y, a2.y, 0.f);
    g_img[0][o+2] = make_float4(a0.z, a1.z, a2.z, 0.f);
    g_img[0][o+3] = make_float4(a0.w, a1.w, a2.w, 0.f);
    g_img[1][o+0] = make_float4(b0.x, b1.x, b2.x, 0.f);
    g_img[1][o+1] = make_float4(b0.y, b1.y, b2.y, 0.f);
    g_img[1][o+2] = make_float4(b0.z, b1.z, b2.z, 0.f);
    g_img[1][o+3] = make_float4(b0.w, b1.w, b2.w, 0.f);
}

// Exact f32 constants as the reference's fp32 trace sees them.
#define ANGC    0.006135923151542565f   // f32(2*pi/1024) == f32(pi/512)
#define SCALEF  162.97466172610083f     // f32(W/(2*pi)) == f32(H/pi) = 512/pi
#define SCALE2F 325.94932345220166f     // 2*SCALEF
#define PIF     3.141592653589793f
#define MAGICF  12582912.0f             // 2^23 + 2^22: float->int round trick

__device__ __forceinline__ float frcp_ap(float x) {
    float r; asm("rcp.approx.f32 %0, %1;" : "=f"(r) : "f"(x)); return r;
}
__device__ __forceinline__ float fsqrt_ap(float x) {
    float r; asm("sqrt.approx.f32 %0, %1;" : "=f"(r) : "f"(x)); return r;
}

// ---- packed fp32x2 primitives (sm_100+) ----
__device__ __forceinline__ u64 pk2(float lo, float hi) {
    u64 r; asm("mov.b64 %0, {%1, %2};" : "=l"(r) : "f"(lo), "f"(hi)); return r;
}
#define UPK2(lo, hi, v) asm("mov.b64 {%0, %1}, %2;" : "=f"(lo), "=f"(hi) : "l"(v))
__device__ __forceinline__ u64 fma2_(u64 a, u64 b, u64 c) {
    u64 d; asm("fma.rn.f32x2 %0, %1, %2, %3;" : "=l"(d) : "l"(a), "l"(b), "l"(c)); return d;
}
__device__ __forceinline__ u64 mul2_(u64 a, u64 b) {
    u64 d; asm("mul.rn.f32x2 %0, %1, %2;" : "=l"(d) : "l"(a), "l"(b)); return d;
}

// ---- scalar SLEEF atan core (pole path only) ----
__device__ __forceinline__ float atan_core_s(float t, float S) {
    float t2 = t * t;
    float u = 0.00282363896258175373f;
    u = fmaf(u, t2, -0.0159569028764963150f);
    u = fmaf(u, t2,  0.0425049886107444763f);
    u = fmaf(u, t2, -0.0748900920152664184f);
    u = fmaf(u, t2,  0.106347933411598205f);
    u = fmaf(u, t2, -0.142027363181114196f);
    u = fmaf(u, t2,  0.199926957488059997f);
    u = fmaf(u, t2, -0.333331018686294555f);
    float st = S * t;
    return fmaf(t2 * u, st, st);
}
__device__ __forceinline__ float atan2_2pi_s(float y, float x) {
    float ax = fabsf(x), ay = fabsf(y);
    float mx = fmaxf(ax, ay), mn = fminf(ax, ay);
    float a = atan_core_s(mn * frcp_ap(mx), SCALEF);
    if (ay > ax)  a = 256.0f - a;
    if (x < 0.f)  a = 512.0f - a;
    if (y < 0.f)  a = 1024.0f - a;
    return a;
}
__device__ __forceinline__ float atan2_pos_s(float y, float x) {
    float mx = fmaxf(x, y), mn = fminf(x, y);
    float a = atan_core_s(mn * frcp_ap(mx), SCALE2F);
    return (y > x) ? (512.0f - a) : a;
}

// Bit-exact replica of the reference fp32 chain for pole-gated samples.
// R10 proved this is load-bearing where 1/sin(phi) amplification is large.
// __noinline__ keeps its ~20 temps out of the hot loop's allocation.
__device__ __noinline__ float2 pole_exact(float r, float dx, float dy, float dz,
                                          const float* __restrict__ R,
                                          const float* __restrict__ t) {
    float rx = __fmul_rn(r, dx);
    float ry = __fmul_rn(r, dy);
    float rz = __fmul_rn(r, dz);
    float px = __fadd_rn(fmaf(__ldg(R+2), rz, fmaf(__ldg(R+1), ry, __fmul_rn(__ldg(R+0), rx))), __ldg(t+0));
    float py = __fadd_rn(fmaf(__ldg(R+5), rz, fmaf(__ldg(R+4), ry, __fmul_rn(__ldg(R+3), rx))), __ldg(t+1));
    float pz = __fadd_rn(fmaf(__ldg(R+8), rz, fmaf(__ldg(R+7), ry, __fmul_rn(__ldg(R+6), rx))), __ldg(t+2));
    float s = __fadd_rn(__fadd_rn(__fmul_rn(px, px), __fmul_rn(py, py)), __fmul_rn(pz, pz));
    float nz = __fdiv_rn(pz, __fsqrt_rn(s));
    nz = fminf(fmaxf(nz, -1.0f), 1.0f);
    float xx = __fmul_rn(nz, nz);
    float yy = fsqrt_ap(__fadd_rn(1.0f, -xx));
    float xpn = __fadd_rn(1.0f, nz);
    float ha = atan2_pos_s(yy, xpn);
    float gy = (nz != -1.0f) ? (ha - 0.5f) : fmaf(PIF, SCALEF, -0.5f);
    float gx = atan2_2pi_s(py, px) - 0.5f;
    return make_float2(gx, gy);
}

__device__ __forceinline__ float3 bisample(const float4* __restrict__ im, float gx, float gy) {
    // Magic-number floor: mantissa low 23 bits = 0x400000 + floor(g), exact.
    float fx = (gx - 0.5f) + MAGICF;
    float fy = (gy - 0.5f) + MAGICF;
    float wx = gx - (fx - MAGICF);
    float wy = gy - (fy - MAGICF);
    int bx = __float_as_int(fx);
    int x0 = bx & (WW - 1);                // 0x400000 is a multiple of 1024
    int x1 = (bx + 1) & (WW - 1);
    int iy = (__float_as_int(fy) & 0x7FFFFF) - 0x400000;   // in [-1, 511]
    int y0 = max(iy, 0);
    int y1 = min(y0 + 1, HH - 1);
    const float4* r0p = im + (y0 << 10);
    const float4* r1p = im + (y1 << 10);
    float4 a = __ldg(r0p + x0);
    float4 b = __ldg(r0p + x1);
    float4 c = __ldg(r1p + x0);
    float4 d = __ldg(r1p + x1);
    float u = 1.0f - wx, vv = 1.0f - wy;
    float w00 = u * vv, w01 = wx * vv, w10 = u * wy, w11 = wx * wy;
    float3 o;
    o.x = fmaf(w00, a.x, fmaf(w01, b.x, fmaf(w10, c.x, w11 * d.x)));
    o.y = fmaf(w00, a.y, fmaf(w01, b.y, fmaf(w10, c.y, w11 * d.y)));
    o.z = fmaf(w00, a.z, fmaf(w10, c.z, fmaf(w01, b.z, w11 * d.z)));
    return o;
}

// One block = one (pixel-tile, view); two depths per loop iteration, packed
// f32x2 math on the lane-pair wherever the chain is elementwise.
__global__ void __launch_bounds__(256, 4)
warp_kernel(const float* __restrict__ R0, const float* __restrict__ t0,
            const float* __restrict__ R1, const float* __restrict__ t1,
            const float* __restrict__ radii, float* __restrict__ out) {
    __shared__ u64 s_r2[DD / 2];
    int tid = threadIdx.x;
    if (tid < DD / 2) {
        float lo = __ldg(radii + 2 * tid), hi = __ldg(radii + 2 * tid + 1);
        s_r2[tid] = ((u64)__float_as_uint(hi) << 32) | (u64)__float_as_uint(lo);
    }
    __syncthreads();

    int v = blockIdx.y;
    int idx = blockIdx.x * blockDim.x + tid;
    int h = idx >> 10;
    int w = idx & (WW - 1);

    // Pixel-center angles, bit-matching the reference.
    float theta = __fmul_rn((float)w + 0.5f, ANGC);
    float phi   = __fmul_rn((float)h + 0.5f, ANGC);
    float st = sinf(theta), ct = cosf(theta);
    float sp = sinf(phi),   cp = cosf(phi);
    float dx = __fmul_rn(sp, ct);
    float dy = __fmul_rn(sp, st);
    float dz = cp;

    const float* R = v ? R1 : R0;
    const float* t = v ? t1 : t0;

    // Hoisted rotated ray q = R*d (cheap-path only; pole path re-derives the
    // exact replica). R scalars die after this block.
    float qx, qy, qz, txs, tys, tzs;
    {
        float r00 = __ldg(R + 0), r01 = __ldg(R + 1), r02 = __ldg(R + 2);
        float r10 = __ldg(R + 3), r11 = __ldg(R + 4), r12 = __ldg(R + 5);
        float r20 = __ldg(R + 6), r21 = __ldg(R + 7), r22 = __ldg(R + 8);
        qx = fmaf(r00, dx, fmaf(r01, dy, r02 * dz));
        qy = fmaf(r10, dx, fmaf(r11, dy, r12 * dz));
        qz = fmaf(r20, dx, fmaf(r21, dy, r22 * dz));
        txs = __ldg(t + 0); tys = __ldg(t + 1); tzs = __ldg(t + 2);
    }
    u64 qx2 = pk2(qx, qx), qy2 = pk2(qy, qy), qz2 = pk2(qz, qz);
    u64 tx2 = pk2(txs, txs), ty2 = pk2(tys, tys), tz2 = pk2(tzs, tzs);

    // SLEEF coefficients, duplicated into both f32x2 lanes (loop-invariant).
    const u64 C0 = pk2( 0.00282363896258175373f,  0.00282363896258175373f);
    const u64 C1 = pk2(-0.0159569028764963150f,  -0.0159569028764963150f);
    const u64 C2 = pk2( 0.0425049886107444763f,   0.0425049886107444763f);
    const u64 C3 = pk2(-0.0748900920152664184f,  -0.0748900920152664184f);
    const u64 C4 = pk2( 0.106347933411598205f,    0.106347933411598205f);
    const u64 C5 = pk2(-0.142027363181114196f,   -0.142027363181114196f);
    const u64 C6 = pk2( 0.199926957488059997f,    0.199926957488059997f);
    const u64 C7 = pk2(-0.333331018686294555f,   -0.333331018686294555f);
    const u64 S2 = pk2(SCALEF, SCALEF);

    // Packed SCALEF*atan(t) for two independent ratios in [0,1]: per-lane op
    // sequence identical to atan_core_s -> bit-compatible with R13.
    auto poly2 = [&](u64 tp) -> u64 {
        u64 t2 = mul2_(tp, tp);
        u64 u = C0;
        u = fma2_(u, t2, C1); u = fma2_(u, t2, C2); u = fma2_(u, t2, C3);
        u = fma2_(u, t2, C4); u = fma2_(u, t2, C5); u = fma2_(u, t2, C6);
        u = fma2_(u, t2, C7);
        u64 stp = mul2_(S2, tp);
        return fma2_(mul2_(t2, u), stp, stp);
    };

    const float4* im = g_img[v];
    float* ob = out + (size_t)(v * 3) * HWSZ + idx;

#pragma unroll 2
    for (int dp = 0; dp < DD / 2; dp++) {
        u64 r2v = s_r2[dp];
        u64 px2 = fma2_(r2v, qx2, tx2);
        u64 py2 = fma2_(r2v, qy2, ty2);
        u64 pz2 = fma2_(r2v, qz2, tz2);
        u64 sxy2 = fma2_(px2, px2, mul2_(py2, py2));
        u64 pzq2 = mul2_(pz2, pz2);

        float px0, px1, py0, py1, pz0, pz1, sx0, sx1, zq0, zq1;
        UPK2(px0, px1, px2); UPK2(py0, py1, py2); UPK2(pz0, pz1, pz2);
        UPK2(sx0, sx1, sxy2); UPK2(zq0, zq1, pzq2);

        // scalar ratio prep per lane (MUFU + min/max are scalar-only)
        float tth0, tth1, tph0, tph1;
        {
            float ax = fabsf(px0), ay = fabsf(py0);
            tth0 = fminf(ax, ay) * frcp_ap(fmaxf(ax, ay));
            float rho = fsqrt_ap(sx0), az = fabsf(pz0);
            tph0 = fminf(az, rho) * frcp_ap(fmaxf(az, rho));
        }
        {
            float ax = fabsf(px1), ay = fabsf(py1);
            tth1 = fminf(ax, ay) * frcp_ap(fmaxf(ax, ay));
            float rho = fsqrt_ap(sx1), az = fabsf(pz1);
            tph1 = fminf(az, rho) * frcp_ap(fmaxf(az, rho));
        }

        u64 ath2 = poly2(pk2(tth0, tth1));
        u64 aph2 = poly2(pk2(tph0, tph1));
        float a0, a1, b0, b1;
        UPK2(a0, a1, ath2); UPK2(b0, b1, aph2);

        // quadrant selects (sx > zq  <=>  rho > |pz|, both nonneg)
        float gx0, gy0, gx1, gy1;
        {
            float a = a0;
            if (fabsf(py0) > fabsf(px0)) a = 256.0f - a;
            if (px0 < 0.f) a = 512.0f - a;
            if (py0 < 0.f) a = 1024.0f - a;
            gx0 = a - 0.5f;
            float b = b0;
            if (sx0 > zq0) b = 256.0f - b;
            if (pz0 < 0.f) b = 512.0f - b;
            gy0 = b - 0.5f;
        }
        {
            float a = a1;
            if (fabsf(py1) > fabsf(px1)) a = 256.0f - a;
            if (px1 < 0.f) a = 512.0f - a;
            if (py1 < 0.f) a = 1024.0f - a;
            gx1 = a - 0.5f;
            float b = b1;
            if (sx1 > zq1) b = 256.0f - b;
            if (pz1 < 0.f) b = 512.0f - b;
            gy1 = b - 0.5f;
        }

        // Pole gate (sin^2(phi_s) < 1/16): rare, warp-coherent; exact replica.
        if (15.0f * sx0 < zq0 || 15.0f * sx1 < zq1) {
            float r0e, r1e;
            UPK2(r0e, r1e, r2v);
            if (15.0f * sx0 < zq0) {
                float2 g = pole_exact(r0e, dx, dy, dz, R, t);
                gx0 = g.x; gy0 = g.y;
            }
            if (15.0f * sx1 < zq1) {
                float2 g = pole_exact(r1e, dx, dy, dz, R, t);
                gx1 = g.x; gy1 = g.y;
            }
        }

        float3 s0 = bisample(im, gx0, gy0);
        float3 s1 = bisample(im, gx1, gy1);
        float* o1 = ob + 6 * HWSZ;
        ob[0 * HWSZ] = s0.x;
        ob[1 * HWSZ] = s0.y;
        ob[2 * HWSZ] = s0.z;
        o1[0 * HWSZ] = s1.x;
        o1[1 * HWSZ] = s1.y;
        o1[2 * HWSZ] = s1.z;
        ob += 12 * HWSZ;
    }
}

extern "C" void kernel_launch(void* const* d_in, const int* in_sizes, int n_in,
                              void* d_out, int out_size) {
    const float* view_ref = (const float*)d_in[0];
    const float* view_inp = (const float*)d_in[1];
    const float* R0 = (const float*)d_in[2];
    const float* t0 = (const float*)d_in[3];
    const float* R1 = (const float*)d_in[4];
    const float* t1 = (const float*)d_in[5];
    const float* radii = (const float*)d_in[6];
    float* out = (float*)d_out;

    pack_kernel<<<(HWSZ / 4 + 255) / 256, 256>>>(view_ref, view_inp);
    dim3 grid((HWSZ + 255) / 256, 2);
    warp_kernel<<<grid, 256>>>(R0, t0, R1, t1, radii, out);
}

// round 15
// speedup vs baseline: 1.0742x; 1.0742x over previous
#include <cuda_runtime.h>

#define HH 512
#define WW 1024
#define DD 32
#define HWSZ (HH*WW)

// Packed RGBA (A unused) copies of the two source views. 16 MB static scratch.
__device__ float4 g_img[2][HWSZ];

__global__ void pack_kernel(const float* __restrict__ ref, const float* __restrict__ inp) {
    int i = blockIdx.x * blockDim.x + threadIdx.x;   // quad index
    if (i >= HWSZ / 4) return;
    const float4* r4 = (const float4*)ref;
    const float4* i4 = (const float4*)inp;
    float4 a0 = r4[i], a1 = r4[i + HWSZ/4], a2 = r4[i + 2*(HWSZ/4)];
    float4 b0 = i4[i], b1 = i4[i + HWSZ/4], b2 = i4[i + 2*(HWSZ/4)];
    int o = i << 2;
    g_img[0][o+0] = make_float4(a0.x, a1.x, a2.x, 0.f);
    g_img[0][o+1] = make_float4(a0.y, a1.y, a2.y, 0.f);
    g_img[0][o+2] = make_float4(a0.z, a1.z, a2.z, 0.f);
    g_img[0][o+3] = make_float4(a0.w, a1.w, a2.w, 0.f);
    g_img[1][o+0] = make_float4(b0.x, b1.x, b2.x, 0.f);
    g_img[1][o+1] = make_float4(b0.y, b1.y, b2.y, 0.f);
    g_img[1][o+2] = make_float4(b0.z, b1.z, b2.z, 0.f);
    g_img[1][o+3] = make_float4(b0.w, b1.w, b2.w, 0.f);
}

// Exact f32 constants as the reference's fp32 trace sees them.
#define ANGC    0.006135923151542565f   // f32(2*pi/1024) == f32(pi/512)
#define SCALEF  162.97466172610083f     // f32(W/(2*pi)) == f32(H/pi) = 512/pi
#define SCALE2F 325.94932345220166f     // 2*SCALEF
#define PIF     3.141592653589793f
#define MAGICF  12582912.0f             // 2^23 + 2^22: float->int round trick

__device__ __forceinline__ float frcp_ap(float x) {
    float r; asm("rcp.approx.f32 %0, %1;" : "=f"(r) : "f"(x)); return r;
}
__device__ __forceinline__ float fsqrt_ap(float x) {
    float r; asm("sqrt.approx.f32 %0, %1;" : "=f"(r) : "f"(x)); return r;
}

// S * atan(t) for t in [0,1]: SLEEF 8-coef minimax (~1 ulp), grid scale folded.
__device__ __forceinline__ float atan_core_s(float t, float S) {
    float t2 = t * t;
    float u = 0.00282363896258175373f;
    u = fmaf(u, t2, -0.0159569028764963150f);
    u = fmaf(u, t2,  0.0425049886107444763f);
    u = fmaf(u, t2, -0.0748900920152664184f);
    u = fmaf(u, t2,  0.106347933411598205f);
    u = fmaf(u, t2, -0.142027363181114196f);
    u = fmaf(u, t2,  0.199926957488059997f);
    u = fmaf(u, t2, -0.333331018686294555f);
    float st = S * t;
    return fmaf(t2 * u, st, st);
}

// SCALEF * mod(atan2(y,x), 2pi): quadrant constants exact (256/512/1024).
__device__ __forceinline__ float atan2_2pi_s(float y, float x) {
    float ax = fabsf(x), ay = fabsf(y);
    float mx = fmaxf(ax, ay), mn = fminf(ax, ay);
    float a = atan_core_s(mn * frcp_ap(mx), SCALEF);
    if (ay > ax)  a = 256.0f - a;
    if (x < 0.f)  a = 512.0f - a;
    if (y < 0.f)  a = 1024.0f - a;
    return a;
}

// SCALEF * atan2(rho, z) for rho >= 0 (polar angle in [0, 512]).
__device__ __forceinline__ float atan2_phi_s(float rho, float z) {
    float az = fabsf(z);
    float mx = fmaxf(az, rho), mn = fminf(az, rho);
    float a = atan_core_s(mn * frcp_ap(mx), SCALEF);
    if (rho > az) a = 256.0f - a;
    if (z < 0.f)  a = 512.0f - a;
    return a;
}

// SCALE2F * atan2(y,x) for y,x >= 0 (pole-path half-angle acos).
__device__ __forceinline__ float atan2_pos_s(float y, float x) {
    float mx = fmaxf(x, y), mn = fminf(x, y);
    float a = atan_core_s(mn * frcp_ap(mx), SCALE2F);
    return (y > x) ? (512.0f - a) : a;
}

// Bit-exact replica of the reference fp32 chain for pole-gated samples (~3%,
// warp-coherent rows). R10 proved this is load-bearing where the 1/sin(phi)
// amplification is large. __noinline__ + re-__ldg of R/t keeps its ~20 temps
// and the 12 R/t scalars OUT of the hot loop's register allocation.
__device__ __noinline__ float2 pole_exact(float r, float dx, float dy, float dz,
                                          const float* __restrict__ R,
                                          const float* __restrict__ t) {
    float rx = __fmul_rn(r, dx);
    float ry = __fmul_rn(r, dy);
    float rz = __fmul_rn(r, dz);
    float px = __fadd_rn(fmaf(__ldg(R+2), rz, fmaf(__ldg(R+1), ry, __fmul_rn(__ldg(R+0), rx))), __ldg(t+0));
    float py = __fadd_rn(fmaf(__ldg(R+5), rz, fmaf(__ldg(R+4), ry, __fmul_rn(__ldg(R+3), rx))), __ldg(t+1));
    float pz = __fadd_rn(fmaf(__ldg(R+8), rz, fmaf(__ldg(R+7), ry, __fmul_rn(__ldg(R+6), rx))), __ldg(t+2));
    float s = __fadd_rn(__fadd_rn(__fmul_rn(px, px), __fmul_rn(py, py)), __fmul_rn(pz, pz));
    float nz = __fdiv_rn(pz, __fsqrt_rn(s));
    nz = fminf(fmaxf(nz, -1.0f), 1.0f);
    float xx = __fmul_rn(nz, nz);
    float yy = fsqrt_ap(__fadd_rn(1.0f, -xx));
    float xpn = __fadd_rn(1.0f, nz);
    float ha = atan2_pos_s(yy, xpn);
    float gy = (nz != -1.0f) ? (ha - 0.5f) : fmaf(PIF, SCALEF, -0.5f);
    float gx = atan2_2pi_s(py, px) - 0.5f;
    return make_float2(gx, gy);
}

__device__ __forceinline__ float3 bisample(const float4* __restrict__ im, float gx, float gy) {
    // Magic-number floor: mantissa low 23 bits = 0x400000 + floor(g), exact.
    float fx = (gx - 0.5f) + MAGICF;
    float fy = (gy - 0.5f) + MAGICF;
    float wx = gx - (fx - MAGICF);
    float wy = gy - (fy - MAGICF);
    int bx = __float_as_int(fx);
    int x0 = bx & (WW - 1);                // 0x400000 is a multiple of 1024
    int x1 = (bx + 1) & (WW - 1);
    int iy = (__float_as_int(fy) & 0x7FFFFF) - 0x400000;   // in [-1, 511]
    int y0 = max(iy, 0);
    int y1 = min(y0 + 1, HH - 1);
    const float4* r0p = im + (y0 << 10);
    const float4* r1p = im + (y1 << 10);
    float4 a = __ldg(r0p + x0);
    float4 b = __ldg(r0p + x1);
    float4 c = __ldg(r1p + x0);
    float4 d = __ldg(r1p + x1);
    float u = 1.0f - wx, vv = 1.0f - wy;
    float w00 = u * vv, w01 = wx * vv, w10 = u * wy, w11 = wx * wy;
    float3 o;
    o.x = fmaf(w00, a.x, fmaf(w01, b.x, fmaf(w10, c.x, w11 * d.x)));
    o.y = fmaf(w00, a.y, fmaf(w01, b.y, fmaf(w10, c.y, w11 * d.y)));
    o.z = fmaf(w00, a.z, fmaf(w10, c.z, fmaf(w01, b.z, w11 * d.z)));
    return o;
}

// One block = one (pixel-tile, view); blockIdx.y selects the view.
__global__ void __launch_bounds__(256, 6)
warp_kernel(const float* __restrict__ R0, const float* __restrict__ t0,
            const float* __restrict__ R1, const float* __restrict__ t1,
            const float* __restrict__ radii, float* __restrict__ out) {
    __shared__ float s_r[DD];
    int tid = threadIdx.x;
    if (tid < DD) s_r[tid] = __ldg(radii + tid);
    __syncthreads();

    int v = blockIdx.y;
    int idx = blockIdx.x * blockDim.x + tid;
    int h = idx >> 10;
    int w = idx & (WW - 1);

    // Pixel-center angles, bit-matching the reference.
    float theta = __fmul_rn((float)w + 0.5f, ANGC);
    float phi   = __fmul_rn((float)h + 0.5f, ANGC);
    float st = sinf(theta), ct = cosf(theta);
    float sp = sinf(phi),   cp = cosf(phi);
    float dx = __fmul_rn(sp, ct);
    float dy = __fmul_rn(sp, st);
    float dz = cp;

    const float* R = v ? R1 : R0;
    const float* t = v ? t1 : t0;

    // Hoisted rotated ray q = R*d (cheap-path only; the pole path re-derives
    // the exact replica from R/t). R scalars die after this block.
    float qx, qy, qz, tx, ty, tz;
    {
        float r00 = __ldg(R + 0), r01 = __ldg(R + 1), r02 = __ldg(R + 2);
        float r10 = __ldg(R + 3), r11 = __ldg(R + 4), r12 = __ldg(R + 5);
        float r20 = __ldg(R + 6), r21 = __ldg(R + 7), r22 = __ldg(R + 8);
        qx = fmaf(r00, dx, fmaf(r01, dy, r02 * dz));
        qy = fmaf(r10, dx, fmaf(r11, dy, r12 * dz));
        qz = fmaf(r20, dx, fmaf(r21, dy, r22 * dz));
        tx = __ldg(t + 0); ty = __ldg(t + 1); tz = __ldg(t + 2);
    }

    const float4* im = g_img[v];
    float* ob = out + (size_t)(v * 3) * HWSZ + idx;

#pragma unroll 2
    for (int d = 0; d < DD; d++) {
        float r = s_r[d];
        float px = fmaf(r, qx, tx);
        float py = fmaf(r, qy, ty);
        float pz = fmaf(r, qz, tz);
        float sxy = fmaf(px, px, py * py);

        float gx, gy;
        // Pole gate: sin^2(phi_sampled) < 1/16  <=>  15*sxy < pz^2.
        // Warp-coherent (lanes share h). 97% take the cheap path.
        if (15.0f * sxy < pz * pz) {
            float2 g = pole_exact(r, dx, dy, dz, R, t);
            gx = g.x; gy = g.y;
        } else {
            // Cheap path: phi = atan2(rho, pz) == acos(nz) — no normalize,
            // no clamp, no yy. All deviations unamplified away from poles.
            float rho = fsqrt_ap(sxy);
            gy = atan2_phi_s(rho, pz) - 0.5f;
            gx = atan2_2pi_s(py, px) - 0.5f;
        }

        float3 smp = bisample(im, gx, gy);
        ob[0 * HWSZ] = smp.x;
        ob[1 * HWSZ] = smp.y;
        ob[2 * HWSZ] = smp.z;
        ob += 6 * HWSZ;
    }
}

extern "C" void kernel_launch(void* const* d_in, const int* in_sizes, int n_in,
                              void* d_out, int out_size) {
    const float* view_ref = (const float*)d_in[0];
    const float* view_inp = (const float*)d_in[1];
    const float* R0 = (const float*)d_in[2];
    const float* t0 = (const float*)d_in[3];
    const float* R1 = (const float*)d_in[4];
    const float* t1 = (const float*)d_in[5];
    const float* radii = (const float*)d_in[6];
    float* out = (float*)d_out;

    pack_kernel<<<(HWSZ / 4 + 255) / 256, 256>>>(view_ref, view_inp);
    dim3 grid((HWSZ + 255) / 256, 2);
    warp_kernel<<<grid, 256>>>(R0, t0, R1, t1, radii, out);
}

// round 16
// speedup vs baseline: 1.0748x; 1.0006x over previous
#include <cuda_runtime.h>

#define HH 512
#define WW 1024
#define DD 32
#define HWSZ (HH*WW)

// Packed RGBA (A unused) copies of the two source views. 16 MB static scratch.
__device__ float4 g_img[2][HWSZ];

__global__ void pack_kernel(const float* __restrict__ ref, const float* __restrict__ inp) {
    int i = blockIdx.x * blockDim.x + threadIdx.x;   // quad index
    if (i >= HWSZ / 4) return;
    const float4* r4 = (const float4*)ref;
    const float4* i4 = (const float4*)inp;
    float4 a0 = r4[i], a1 = r4[i + HWSZ/4], a2 = r4[i + 2*(HWSZ/4)];
    float4 b0 = i4[i], b1 = i4[i + HWSZ/4], b2 = i4[i + 2*(HWSZ/4)];
    int o = i << 2;
    g_img[0][o+0] = make_float4(a0.x, a1.x, a2.x, 0.f);
    g_img[0][o+1] = make_float4(a0.y, a1.y, a2.y, 0.f);
    g_img[0][o+2] = make_float4(a0.z, a1.z, a2.z, 0.f);
    g_img[0][o+3] = make_float4(a0.w, a1.w, a2.w, 0.f);
    g_img[1][o+0] = make_float4(b0.x, b1.x, b2.x, 0.f);
    g_img[1][o+1] = make_float4(b0.y, b1.y, b2.y, 0.f);
    g_img[1][o+2] = make_float4(b0.z, b1.z, b2.z, 0.f);
    g_img[1][o+3] = make_float4(b0.w, b1.w, b2.w, 0.f);
}

// Exact f32 constants as the reference's fp32 trace sees them.
#define ANGC    0.006135923151542565f   // f32(2*pi/1024) == f32(pi/512)
#define SCALEF  162.97466172610083f     // f32(W/(2*pi)) == f32(H/pi) = 512/pi
#define SCALE2F 325.94932345220166f     // 2*SCALEF
#define PIF     3.141592653589793f
#define MAGICF  12582912.0f             // 2^23 + 2^22: float->int round trick

__device__ __forceinline__ float frcp_ap(float x) {
    float r; asm("rcp.approx.f32 %0, %1;" : "=f"(r) : "f"(x)); return r;
}
__device__ __forceinline__ float fsqrt_ap(float x) {
    float r; asm("sqrt.approx.f32 %0, %1;" : "=f"(r) : "f"(x)); return r;
}

// S * atan(t) for t in [0,1]: SLEEF 8-coef minimax (~1 ulp), grid scale folded.
__device__ __forceinline__ float atan_core_s(float t, float S) {
    float t2 = t * t;
    float u = 0.00282363896258175373f;
    u = fmaf(u, t2, -0.0159569028764963150f);
    u = fmaf(u, t2,  0.0425049886107444763f);
    u = fmaf(u, t2, -0.0748900920152664184f);
    u = fmaf(u, t2,  0.106347933411598205f);
    u = fmaf(u, t2, -0.142027363181114196f);
    u = fmaf(u, t2,  0.199926957488059997f);
    u = fmaf(u, t2, -0.333331018686294555f);
    float st = S * t;
    return fmaf(t2 * u, st, st);
}

// SCALEF * mod(atan2(y,x), 2pi): quadrant constants exact (256/512/1024).
__device__ __forceinline__ float atan2_2pi_s(float y, float x) {
    float ax = fabsf(x), ay = fabsf(y);
    float mx = fmaxf(ax, ay), mn = fminf(ax, ay);
    float a = atan_core_s(mn * frcp_ap(mx), SCALEF);
    if (ay > ax)  a = 256.0f - a;
    if (x < 0.f)  a = 512.0f - a;
    if (y < 0.f)  a = 1024.0f - a;
    return a;
}

// SCALEF * atan2(rho, z) for rho >= 0 (polar angle in [0, 512]).
__device__ __forceinline__ float atan2_phi_s(float rho, float z) {
    float az = fabsf(z);
    float mx = fmaxf(az, rho), mn = fminf(az, rho);
    float a = atan_core_s(mn * frcp_ap(mx), SCALEF);
    if (rho > az) a = 256.0f - a;
    if (z < 0.f)  a = 512.0f - a;
    return a;
}

// SCALE2F * atan2(y,x) for y,x >= 0 (pole-path half-angle acos).
__device__ __forceinline__ float atan2_pos_s(float y, float x) {
    float mx = fmaxf(x, y), mn = fminf(x, y);
    float a = atan_core_s(mn * frcp_ap(mx), SCALE2F);
    return (y > x) ? (512.0f - a) : a;
}

// Bit-exact replica of the reference fp32 chain for pole-gated samples (~3%,
// warp-coherent rows). R10 proved this is load-bearing where the 1/sin(phi)
// amplification is large. __noinline__ + re-__ldg of R/t keeps its temps and
// the 12 R/t scalars OUT of the hot loop's register allocation.
__device__ __noinline__ float2 pole_exact(float r, float dx, float dy, float dz,
                                          const float* __restrict__ R,
                                          const float* __restrict__ t) {
    float rx = __fmul_rn(r, dx);
    float ry = __fmul_rn(r, dy);
    float rz = __fmul_rn(r, dz);
    float px = __fadd_rn(fmaf(__ldg(R+2), rz, fmaf(__ldg(R+1), ry, __fmul_rn(__ldg(R+0), rx))), __ldg(t+0));
    float py = __fadd_rn(fmaf(__ldg(R+5), rz, fmaf(__ldg(R+4), ry, __fmul_rn(__ldg(R+3), rx))), __ldg(t+1));
    float pz = __fadd_rn(fmaf(__ldg(R+8), rz, fmaf(__ldg(R+7), ry, __fmul_rn(__ldg(R+6), rx))), __ldg(t+2));
    float s = __fadd_rn(__fadd_rn(__fmul_rn(px, px), __fmul_rn(py, py)), __fmul_rn(pz, pz));
    float nz = __fdiv_rn(pz, __fsqrt_rn(s));
    nz = fminf(fmaxf(nz, -1.0f), 1.0f);
    float xx = __fmul_rn(nz, nz);
    float yy = fsqrt_ap(__fadd_rn(1.0f, -xx));
    float xpn = __fadd_rn(1.0f, nz);
    float ha = atan2_pos_s(yy, xpn);
    float gy = (nz != -1.0f) ? (ha - 0.5f) : fmaf(PIF, SCALEF, -0.5f);
    float gx = atan2_2pi_s(py, px) - 0.5f;
    return make_float2(gx, gy);
}

__device__ __forceinline__ float3 bisample(const float4* __restrict__ im, float gx, float gy) {
    // Magic-number floor: mantissa low 23 bits = 0x400000 + floor(g), exact.
    float fx = (gx - 0.5f) + MAGICF;
    float fy = (gy - 0.5f) + MAGICF;
    float wx = gx - (fx - MAGICF);
    float wy = gy - (fy - MAGICF);
    int bx = __float_as_int(fx);
    int x0 = bx & (WW - 1);                // 0x400000 is a multiple of 1024
    int x1 = (bx + 1) & (WW - 1);
    int iy = (__float_as_int(fy) & 0x7FFFFF) - 0x400000;   // in [-1, 511]
    int y0 = max(iy, 0);
    int y1 = min(y0 + 1, HH - 1);
    const float4* r0p = im + (y0 << 10);
    const float4* r1p = im + (y1 << 10);
    float4 a = __ldg(r0p + x0);
    float4 b = __ldg(r0p + x1);
    float4 c = __ldg(r1p + x0);
    float4 d = __ldg(r1p + x1);
    float u = 1.0f - wx, vv = 1.0f - wy;
    float w00 = u * vv, w01 = wx * vv, w10 = u * wy, w11 = wx * wy;
    float3 o;
    o.x = fmaf(w00, a.x, fmaf(w01, b.x, fmaf(w10, c.x, w11 * d.x)));
    o.y = fmaf(w00, a.y, fmaf(w01, b.y, fmaf(w10, c.y, w11 * d.y)));
    o.z = fmaf(w00, a.z, fmaf(w10, c.z, fmaf(w01, b.z, w11 * d.z)));
    return o;
}

// One block = one (pixel-tile, view); blockIdx.y selects the view.
// Per-depth angles are computed INCREMENTALLY from per-pixel base angles:
//   azimuth: theta_s = theta0 + atan2(cA, r*cC + cB)   (cA r-independent)
//   polar:   phi_s   = phi0 + atan(small ratio)        (deg-9 Taylor)
__global__ void __launch_bounds__(256, 6)
warp_kernel(const float* __restrict__ R0, const float* __restrict__ t0,
            const float* __restrict__ R1, const float* __restrict__ t1,
            const float* __restrict__ radii, float* __restrict__ out) {
    __shared__ float s_r[DD];
    int tid = threadIdx.x;
    if (tid < DD) s_r[tid] = __ldg(radii + tid);
    __syncthreads();

    int v = blockIdx.y;
    int idx = blockIdx.x * blockDim.x + tid;
    int h = idx >> 10;
    int w = idx & (WW - 1);

    // Pixel-center angles, bit-matching the reference.
    float theta = __fmul_rn((float)w + 0.5f, ANGC);
    float phi   = __fmul_rn((float)h + 0.5f, ANGC);
    float st = sinf(theta), ct = cosf(theta);
    float sp = sinf(phi),   cp = cosf(phi);
    float dx = __fmul_rn(sp, ct);
    float dy = __fmul_rn(sp, st);
    float dz = cp;

    const float* R = v ? R1 : R0;
    const float* t = v ? t1 : t0;

    // Per-pixel geometric setup (q = R*d; line-coefficients for p = r*q + t).
    float qz, tz, cA, acA, sA, cB, cB2, cC, cD, rho0, th0m, ph0m;
    {
        float r00 = __ldg(R + 0), r01 = __ldg(R + 1), r02 = __ldg(R + 2);
        float r10 = __ldg(R + 3), r11 = __ldg(R + 4), r12 = __ldg(R + 5);
        float r20 = __ldg(R + 6), r21 = __ldg(R + 7), r22 = __ldg(R + 8);
        float qx = fmaf(r00, dx, fmaf(r01, dy, r02 * dz));
        float qy = fmaf(r10, dx, fmaf(r11, dy, r12 * dz));
        qz = fmaf(r20, dx, fmaf(r21, dy, r22 * dz));
        float tx = __ldg(t + 0), ty = __ldg(t + 1);
        tz = __ldg(t + 2);
        cA  = fmaf(qx, ty, -(qy * tx));          // cross(q_xy, t_xy), r-indep
        acA = fabsf(cA);
        sA  = (cA < 0.f) ? -1.0f : 1.0f;
        cB  = fmaf(qx, tx, qy * ty);             // dot(q_xy, t_xy)
        cB2 = cB + cB;
        cC  = fmaf(qx, qx, qy * qy);             // rho0^2
        cD  = fmaf(tx, tx, ty * ty);
        rho0 = fsqrt_ap(cC);
        th0m = atan2_2pi_s(qy, qx) - 0.5f;       // scaled base azimuth - 0.5
        ph0m = atan2_phi_s(rho0, qz) - 0.5f;     // scaled base polar  - 0.5
    }

    const float4* im = g_img[v];
    float* ob = out + (size_t)(v * 3) * HWSZ + idx;

#pragma unroll 2
    for (int d = 0; d < DD; d++) {
        float r = s_r[d];
        float den = fmaf(r, cC, cB);                    // dot(q_xy, p_xy)
        float sxy = fmaf(r, fmaf(r, cC, cB2), cD);      // |p_xy|^2
        float pz  = fmaf(r, qz, tz);
        float zq  = pz * pz;

        float gx, gy;
        // Pole gate: sin^2(phi_s) < 1/16, or degenerate azimuth denominator
        // (den<=0 provably implies rho_s <= |t_xy|, i.e. also near-pole).
        // Warp-coherent; ~3% take the exact-replica path.
        if (15.0f * sxy < zq || den <= 0.0f) {
            float2 g = pole_exact(r, dx, dy, dz, R, t);
            gx = g.x; gy = g.y;
        } else {
            // Azimuth increment: atan2(cA, den), |cA| and sign hoisted.
            float mn = fminf(acA, den), mx = fmaxf(acA, den);
            float a = atan_core_s(mn * frcp_ap(mx), SCALEF);
            if (acA > den) a = 256.0f - a;
            gx = fmaf(sA, a, th0m);
            // Polar increment: tan(dphi) = (rho_s*qz - pz*rho0)/(pz*qz + rho_s*rho0),
            // |ratio| <= ~0.3 -> deg-9 Taylor (err < 2e-7 rad).
            float rs  = fsqrt_ap(sxy);
            float num = fmaf(rs, qz, -(pz * rho0));
            float dn2 = fmaf(pz, qz, rs * rho0);
            float tq  = num * frcp_ap(dn2);
            float t2  = tq * tq;
            float u = fmaf(0.111111111f, t2, -0.142857143f);
            u = fmaf(u, t2, 0.2f);
            u = fmaf(u, t2, -0.333333333f);
            float stq = SCALEF * tq;
            gy = ph0m + fmaf(t2 * u, stq, stq);
        }

        float3 smp = bisample(im, gx, gy);
        ob[0 * HWSZ] = smp.x;
        ob[1 * HWSZ] = smp.y;
        ob[2 * HWSZ] = smp.z;
        ob += 6 * HWSZ;
    }
}

extern "C" void kernel_launch(void* const* d_in, const int* in_sizes, int n_in,
                              void* d_out, int out_size) {
    const float* view_ref = (const float*)d_in[0];
    const float* view_inp = (const float*)d_in[1];
    const float* R0 = (const float*)d_in[2];
    const float* t0 = (const float*)d_in[3];
    const float* R1 = (const float*)d_in[4];
    const float* t1 = (const float*)d_in[5];
    const float* radii = (const float*)d_in[6];
    float* out = (float*)d_out;

    pack_kernel<<<(HWSZ / 4 + 255) / 256, 256>>>(view_ref, view_inp);
    dim3 grid((HWSZ + 255) / 256, 2);
    warp_kernel<<<grid, 256>>>(R0, t0, R1, t1, radii, out);
}

// round 17
// speedup vs baseline: 1.1133x; 1.0358x over previous
#include <cuda_runtime.h>

#define HH 512
#define WW 1024
#define DD 32
#define HWSZ (HH*WW)

// Row split: equator rows [62, 449] (388 rows) are provably pole-safe for all
// depths; pole bands [0,61] & [450,511] (124 rows) carry the per-sample gate.
#define EQ_ROWS 388
#define EQ_BLKS (EQ_ROWS * 4)      // 1552
#define PO_ROWS 124
#define PO_BLKS (PO_ROWS * 4)      // 496

// Packed RGBA (A unused) copies of the two source views. 16 MB static scratch.
__device__ float4 g_img[2][HWSZ];

__global__ void pack_kernel(const float* __restrict__ ref, const float* __restrict__ inp) {
    int i = blockIdx.x * blockDim.x + threadIdx.x;   // quad index
    if (i >= HWSZ / 4) return;
    const float4* r4 = (const float4*)ref;
    const float4* i4 = (const float4*)inp;
    float4 a0 = r4[i], a1 = r4[i + HWSZ/4], a2 = r4[i + 2*(HWSZ/4)];
    float4 b0 = i4[i], b1 = i4[i + HWSZ/4], b2 = i4[i + 2*(HWSZ/4)];
    int o = i << 2;
    g_img[0][o+0] = make_float4(a0.x, a1.x, a2.x, 0.f);
    g_img[0][o+1] = make_float4(a0.y, a1.y, a2.y, 0.f);
    g_img[0][o+2] = make_float4(a0.z, a1.z, a2.z, 0.f);
    g_img[0][o+3] = make_float4(a0.w, a1.w, a2.w, 0.f);
    g_img[1][o+0] = make_float4(b0.x, b1.x, b2.x, 0.f);
    g_img[1][o+1] = make_float4(b0.y, b1.y, b2.y, 0.f);
    g_img[1][o+2] = make_float4(b0.z, b1.z, b2.z, 0.f);
    g_img[1][o+3] = make_float4(b0.w, b1.w, b2.w, 0.f);
}

// Exact f32 constants as the reference's fp32 trace sees them.
#define ANGC    0.006135923151542565f   // f32(2*pi/1024) == f32(pi/512)
#define SCALEF  162.97466172610083f     // f32(W/(2*pi)) == f32(H/pi) = 512/pi
#define SCALE2F 325.94932345220166f     // 2*SCALEF
#define PIF     3.141592653589793f
#define MAGICF  12582912.0f             // 2^23 + 2^22: float->int round trick

__device__ __forceinline__ float frcp_ap(float x) {
    float r; asm("rcp.approx.f32 %0, %1;" : "=f"(r) : "f"(x)); return r;
}
__device__ __forceinline__ float fsqrt_ap(float x) {
    float r; asm("sqrt.approx.f32 %0, %1;" : "=f"(r) : "f"(x)); return r;
}

// S * atan(t) for t in [0,1]: SLEEF 8-coef minimax (~1 ulp), grid scale folded.
__device__ __forceinline__ float atan_core_s(float t, float S) {
    float t2 = t * t;
    float u = 0.00282363896258175373f;
    u = fmaf(u, t2, -0.0159569028764963150f);
    u = fmaf(u, t2,  0.0425049886107444763f);
    u = fmaf(u, t2, -0.0748900920152664184f);
    u = fmaf(u, t2,  0.106347933411598205f);
    u = fmaf(u, t2, -0.142027363181114196f);
    u = fmaf(u, t2,  0.199926957488059997f);
    u = fmaf(u, t2, -0.333331018686294555f);
    float st = S * t;
    return fmaf(t2 * u, st, st);
}

// SCALEF * mod(atan2(y,x), 2pi): quadrant constants exact (256/512/1024).
__device__ __forceinline__ float atan2_2pi_s(float y, float x) {
    float ax = fabsf(x), ay = fabsf(y);
    float mx = fmaxf(ax, ay), mn = fminf(ax, ay);
    float a = atan_core_s(mn * frcp_ap(mx), SCALEF);
    if (ay > ax)  a = 256.0f - a;
    if (x < 0.f)  a = 512.0f - a;
    if (y < 0.f)  a = 1024.0f - a;
    return a;
}

// SCALEF * atan2(rho, z) for rho >= 0 (polar angle in [0, 512]).
__device__ __forceinline__ float atan2_phi_s(float rho, float z) {
    float az = fabsf(z);
    float mx = fmaxf(az, rho), mn = fminf(az, rho);
    float a = atan_core_s(mn * frcp_ap(mx), SCALEF);
    if (rho > az) a = 256.0f - a;
    if (z < 0.f)  a = 512.0f - a;
    return a;
}

// SCALE2F * atan2(y,x) for y,x >= 0 (pole-path half-angle acos).
__device__ __forceinline__ float atan2_pos_s(float y, float x) {
    float mx = fmaxf(x, y), mn = fminf(x, y);
    float a = atan_core_s(mn * frcp_ap(mx), SCALE2F);
    return (y > x) ? (512.0f - a) : a;
}

// Bit-exact replica of the reference fp32 chain for pole-gated samples.
// R10 proved this is load-bearing where the 1/sin(phi) amplification is large.
// __noinline__ + re-__ldg of R/t keeps its temps out of the hot loop.
__device__ __noinline__ float2 pole_exact(float r, float dx, float dy, float dz,
                                          const float* __restrict__ R,
                                          const float* __restrict__ t) {
    float rx = __fmul_rn(r, dx);
    float ry = __fmul_rn(r, dy);
    float rz = __fmul_rn(r, dz);
    float px = __fadd_rn(fmaf(__ldg(R+2), rz, fmaf(__ldg(R+1), ry, __fmul_rn(__ldg(R+0), rx))), __ldg(t+0));
    float py = __fadd_rn(fmaf(__ldg(R+5), rz, fmaf(__ldg(R+4), ry, __fmul_rn(__ldg(R+3), rx))), __ldg(t+1));
    float pz = __fadd_rn(fmaf(__ldg(R+8), rz, fmaf(__ldg(R+7), ry, __fmul_rn(__ldg(R+6), rx))), __ldg(t+2));
    float s = __fadd_rn(__fadd_rn(__fmul_rn(px, px), __fmul_rn(py, py)), __fmul_rn(pz, pz));
    float nz = __fdiv_rn(pz, __fsqrt_rn(s));
    nz = fminf(fmaxf(nz, -1.0f), 1.0f);
    float xx = __fmul_rn(nz, nz);
    float yy = fsqrt_ap(__fadd_rn(1.0f, -xx));
    float xpn = __fadd_rn(1.0f, nz);
    float ha = atan2_pos_s(yy, xpn);
    float gy = (nz != -1.0f) ? (ha - 0.5f) : fmaf(PIF, SCALEF, -0.5f);
    float gx = atan2_2pi_s(py, px) - 0.5f;
    return make_float2(gx, gy);
}

__device__ __forceinline__ float3 bisample(const float4* __restrict__ im, float gx, float gy) {
    // Magic-number floor: mantissa low 23 bits = 0x400000 + floor(g), exact.
    float fx = (gx - 0.5f) + MAGICF;
    float fy = (gy - 0.5f) + MAGICF;
    float wx = gx - (fx - MAGICF);
    float wy = gy - (fy - MAGICF);
    int bx = __float_as_int(fx);
    int x0 = bx & (WW - 1);                // 0x400000 is a multiple of 1024
    int x1 = (bx + 1) & (WW - 1);
    int iy = (__float_as_int(fy) & 0x7FFFFF) - 0x400000;   // in [-1, 511]
    int y0 = max(iy, 0);
    int y1 = min(y0 + 1, HH - 1);
    const float4* r0p = im + (y0 << 10);
    const float4* r1p = im + (y1 << 10);
    float4 a = __ldg(r0p + x0);
    float4 b = __ldg(r0p + x1);
    float4 c = __ldg(r1p + x0);
    float4 d = __ldg(r1p + x1);
    float u = 1.0f - wx, vv = 1.0f - wy;
    float w00 = u * vv, w01 = wx * vv, w10 = u * wy, w11 = wx * wy;
    float3 o;
    o.x = fmaf(w00, a.x, fmaf(w01, b.x, fmaf(w10, c.x, w11 * d.x)));
    o.y = fmaf(w00, a.y, fmaf(w01, b.y, fmaf(w10, c.y, w11 * d.y)));
    o.z = fmaf(w00, a.z, fmaf(w10, c.z, fmaf(w01, b.z, w11 * d.z)));
    return o;
}

// Depth sweep for one (pixel, view). GATED=false: rows where sin(phi_s)>=~0.25
// is guaranteed for every depth -> no per-sample gate, no pole-call liveness.
template<bool GATED>
__device__ __forceinline__ void sweep(int idx, const float* __restrict__ R,
                                      const float* __restrict__ t,
                                      const float* __restrict__ s_r,
                                      const float4* __restrict__ im,
                                      float* __restrict__ ob) {
    int h = idx >> 10;
    int w = idx & (WW - 1);

    // Pixel-center angles, bit-matching the reference.
    float theta = __fmul_rn((float)w + 0.5f, ANGC);
    float phi   = __fmul_rn((float)h + 0.5f, ANGC);
    float st = sinf(theta), ct = cosf(theta);
    float sp = sinf(phi),   cp = cosf(phi);
    float dx = __fmul_rn(sp, ct);
    float dy = __fmul_rn(sp, st);
    float dz = cp;

    // Per-pixel geometric setup (q = R*d; line coefficients for p = r*q + t).
    float qz, tz, acA, sA, cB, cB2, cC, cD, rho0, th0m, ph0m;
    {
        float r00 = __ldg(R + 0), r01 = __ldg(R + 1), r02 = __ldg(R + 2);
        float r10 = __ldg(R + 3), r11 = __ldg(R + 4), r12 = __ldg(R + 5);
        float r20 = __ldg(R + 6), r21 = __ldg(R + 7), r22 = __ldg(R + 8);
        float qx = fmaf(r00, dx, fmaf(r01, dy, r02 * dz));
        float qy = fmaf(r10, dx, fmaf(r11, dy, r12 * dz));
        qz = fmaf(r20, dx, fmaf(r21, dy, r22 * dz));
        float tx = __ldg(t + 0), ty = __ldg(t + 1);
        tz = __ldg(t + 2);
        float cA = fmaf(qx, ty, -(qy * tx));     // cross(q_xy, t_xy), r-indep
        acA = fabsf(cA);
        sA  = (cA < 0.f) ? -1.0f : 1.0f;
        cB  = fmaf(qx, tx, qy * ty);             // dot(q_xy, t_xy)
        cB2 = cB + cB;
        cC  = fmaf(qx, qx, qy * qy);             // rho0^2
        cD  = fmaf(tx, tx, ty * ty);
        rho0 = fsqrt_ap(cC);
        th0m = atan2_2pi_s(qy, qx) - 0.5f;       // scaled base azimuth - 0.5
        ph0m = atan2_phi_s(rho0, qz) - 0.5f;     // scaled base polar  - 0.5
    }

#pragma unroll 2
    for (int d = 0; d < DD; d++) {
        float r = s_r[d];
        float den = fmaf(r, cC, cB);                    // dot(q_xy, p_xy)
        float sxy = fmaf(r, fmaf(r, cC, cB2), cD);      // |p_xy|^2
        float pz  = fmaf(r, qz, tz);

        float gx, gy;
        bool cheap = true;
        if (GATED) cheap = !(15.0f * sxy < pz * pz);    // sin^2(phi_s) >= 1/16
        if (cheap) {
            // Azimuth increment: full-quadrant atan2(cA, den), sign hoisted.
            float aden = fabsf(den);
            float mn = fminf(acA, aden), mx = fmaxf(acA, aden);
            float a = atan_core_s(mn * frcp_ap(mx), SCALEF);
            if (acA > aden) a = 256.0f - a;
            if (den < 0.f)  a = 512.0f - a;
            gx = fmaf(sA, a, th0m);
            // Polar increment: tan(dphi) = (rho_s*qz - pz*rho0)/(pz*qz + rho_s*rho0),
            // |ratio| <= ~0.23 -> deg-7 Taylor (err < 1e-8 rad).
            float rs  = fsqrt_ap(sxy);
            float num = fmaf(rs, qz, -(pz * rho0));
            float dn2 = fmaf(pz, qz, rs * rho0);
            float tq  = num * frcp_ap(dn2);
            float t2  = tq * tq;
            float u = fmaf(-0.142857143f, t2, 0.2f);
            u = fmaf(u, t2, -0.333333333f);
            float stq = SCALEF * tq;
            gy = ph0m + fmaf(t2 * u, stq, stq);
        } else {
            float2 g = pole_exact(r, dx, dy, dz, R, t);
            gx = g.x; gy = g.y;
        }

        float3 smp = bisample(im, gx, gy);
        ob[0 * HWSZ] = smp.x;
        ob[1 * HWSZ] = smp.y;
        ob[2 * HWSZ] = smp.z;
        ob += 6 * HWSZ;
    }
}

// Block-uniform specialization: blocks [0,1552) = equator rows (gate-free);
// blocks [1552,2048) = pole bands (per-sample gate + exact replica).
__global__ void __launch_bounds__(256, 6)
warp_kernel(const float* __restrict__ R0, const float* __restrict__ t0,
            const float* __restrict__ R1, const float* __restrict__ t1,
            const float* __restrict__ radii, float* __restrict__ out) {
    __shared__ float s_r[DD];
    int tid = threadIdx.x;
    if (tid < DD) s_r[tid] = __ldg(radii + tid);
    __syncthreads();

    int v = blockIdx.y;
    const float* R = v ? R1 : R0;
    const float* t = v ? t1 : t0;
    const float4* im = g_img[v];
    float* ov = out + (size_t)(v * 3) * HWSZ;

    int bx = blockIdx.x;
    if (bx < EQ_BLKS) {
        int h  = 62 + bx % EQ_ROWS;
        int wc = bx / EQ_ROWS;
        int idx = (h << 10) + wc * 256 + tid;
        sweep<false>(idx, R, t, s_r, im, ov + idx);
    } else {
        int b2 = bx - EQ_BLKS;
        int rr = b2 % PO_ROWS;
        int h  = (rr < 62) ? rr : (EQ_ROWS + rr);   // 0..61 and 450..511
        int wc = b2 / PO_ROWS;
        int idx = (h << 10) + wc * 256 + tid;
        sweep<true>(idx, R, t, s_r, im, ov + idx);
    }
}

extern "C" void kernel_launch(void* const* d_in, const int* in_sizes, int n_in,
                              void* d_out, int out_size) {
    const float* view_ref = (const float*)d_in[0];
    const float* view_inp = (const float*)d_in[1];
    const float* R0 = (const float*)d_in[2];
    const float* t0 = (const float*)d_in[3];
    const float* R1 = (const float*)d_in[4];
    const float* t1 = (const float*)d_in[5];
    const float* radii = (const float*)d_in[6];
    float* out = (float*)d_out;

    pack_kernel<<<(HWSZ / 4 + 255) / 256, 256>>>(view_ref, view_inp);
    dim3 grid(EQ_BLKS + PO_BLKS, 2);
    warp_kernel<<<grid, 256>>>(R0, t0, R1, t1, radii, out);
}